// round 1
// baseline (speedup 1.0000x reference)
#include <cuda_runtime.h>
#include <math.h>

// Problem constants: B=8, L=1024, D=1024, F=4096, nh=8, hs=128, M=B*L=8192
#define BM 64
#define BN 64
#define BK 16

// Scratch (static device globals; no runtime allocation)
__device__ float g_ln[8388608];        // 8192*1024   LN output (reused for LN1 and LN2)
__device__ float g_qkv[25165824];      // 8192*3072   QKV
__device__ float g_scores[67108864];   // 64*1024*1024  S, then P (in-place softmax)
__device__ float g_qer[67108864];      // 64*1024*1024  QEr
__device__ float g_y[8388608];         // 8192*1024   attention output (pre W_o)
__device__ float g_h[33554432];        // 8192*4096   MLP hidden

// ---------------------------------------------------------------------------
// Generic tiled fp32 GEMM: C = A(MxK) * op(B) (+bias)(+gelu / +residual)
//   TRANSB=false: B is KxN row-major.  TRANSB=true: B is NxK row-major (C=A*B^T)
// Batched via blockIdx.z: z -> hi=z/8, lo=z%8 with independent hi/lo strides.
// epilogue: 0=none, 1=+bias, 2=+bias then exact GELU, 3=+bias +residual
// tri: 0=full, 1=lower-tri skip (skip tiles with n0>m0),
//      2=anti-tri skip (skip tiles with m0+n0 < N-BM-BN+1), 3=causal K bound
// ---------------------------------------------------------------------------
template <bool TRANSB>
__global__ void __launch_bounds__(256)
gemm_kernel(const float* __restrict__ A, int lda, long long sAhi, long long sAlo,
            const float* __restrict__ Bm, int ldb, long long sBhi, long long sBlo,
            float* __restrict__ C, int ldc, long long sChi, long long sClo,
            int M, int N, int K,
            const float* __restrict__ bias,
            const float* __restrict__ resid,
            int epilogue, int tri)
{
    const int n0 = blockIdx.x * BN;
    const int m0 = blockIdx.y * BM;
    if (tri == 1 && n0 > m0) return;                       // strictly above causal diag
    if (tri == 2 && (m0 + n0) < (N - BM - BN + 1)) return; // never-read anti-triangle
    const int kmax = (tri == 3) ? min(K, m0 + BM) : K;

    const int z  = blockIdx.z;
    const int hi = z >> 3;
    const int lo = z & 7;
    A  += hi * sAhi + lo * sAlo;
    Bm += hi * sBhi + lo * sBlo;
    const long long coff = hi * sChi + lo * sClo;

    __shared__ float As[BK][BM + 4];
    __shared__ float Bs[BK][BN + 4];

    const int tid = threadIdx.x;
    const int tx = tid & 15;
    const int ty = tid >> 4;
    const int lr = tid >> 2;         // 0..63 (tile row for transposed loads)
    const int lc = (tid & 3) * 4;    // 0,4,8,12 (k segment)

    float acc[4][4] = {};

    const float* Aload = A + (size_t)(m0 + lr) * lda + lc;
    const float* BloadT = TRANSB ? (Bm + (size_t)(n0 + lr) * ldb + lc) : nullptr;
    const float* BloadN = TRANSB ? nullptr
                                 : (Bm + (size_t)(tid >> 4) * ldb + n0 + (tid & 15) * 4);

    for (int k0 = 0; k0 < kmax; k0 += BK) {
        float4 av = *(const float4*)(Aload + k0);
        As[lc + 0][lr] = av.x;
        As[lc + 1][lr] = av.y;
        As[lc + 2][lr] = av.z;
        As[lc + 3][lr] = av.w;
        if (TRANSB) {
            float4 bv = *(const float4*)(BloadT + k0);
            Bs[lc + 0][lr] = bv.x;
            Bs[lc + 1][lr] = bv.y;
            Bs[lc + 2][lr] = bv.z;
            Bs[lc + 3][lr] = bv.w;
        } else {
            float4 bv = *(const float4*)(BloadN + (size_t)k0 * ldb);
            *(float4*)&Bs[tid >> 4][(tid & 15) * 4] = bv;
        }
        __syncthreads();
#pragma unroll
        for (int kk = 0; kk < BK; kk++) {
            float4 a4 = *(const float4*)&As[kk][ty * 4];
            float4 b4 = *(const float4*)&Bs[kk][tx * 4];
            float a[4] = {a4.x, a4.y, a4.z, a4.w};
            float b[4] = {b4.x, b4.y, b4.z, b4.w};
#pragma unroll
            for (int i = 0; i < 4; i++)
#pragma unroll
                for (int j = 0; j < 4; j++)
                    acc[i][j] = fmaf(a[i], b[j], acc[i][j]);
        }
        __syncthreads();
    }

    float4 bz = make_float4(0.f, 0.f, 0.f, 0.f);
    if (epilogue != 0) bz = *(const float4*)(bias + n0 + tx * 4);
#pragma unroll
    for (int i = 0; i < 4; i++) {
        const size_t ci = (size_t)coff + (size_t)(m0 + ty * 4 + i) * ldc + n0 + tx * 4;
        float4 o;
        o.x = acc[i][0] + bz.x;
        o.y = acc[i][1] + bz.y;
        o.z = acc[i][2] + bz.z;
        o.w = acc[i][3] + bz.w;
        if (epilogue == 2) {              // exact GELU: x * Phi(x)
            o.x *= normcdff(o.x);
            o.y *= normcdff(o.y);
            o.z *= normcdff(o.z);
            o.w *= normcdff(o.w);
        } else if (epilogue == 3) {       // + residual
            const float4 r = *(const float4*)(resid + ci);
            o.x += r.x; o.y += r.y; o.z += r.z; o.w += r.w;
        }
        *(float4*)(C + ci) = o;
    }
}

// ---------------------------------------------------------------------------
// LayerNorm over rows of length 1024. One block (256 threads) per row.
// ---------------------------------------------------------------------------
__global__ void __launch_bounds__(256)
ln_kernel(const float* __restrict__ x, const float* __restrict__ g,
          const float* __restrict__ b, float* __restrict__ out)
{
    const int row = blockIdx.x;
    const int tid = threadIdx.x;
    const float4 xv = ((const float4*)(x + (size_t)row * 1024))[tid];

    float s  = xv.x + xv.y + xv.z + xv.w;
    float ss = xv.x * xv.x + xv.y * xv.y + xv.z * xv.z + xv.w * xv.w;
#pragma unroll
    for (int o = 16; o; o >>= 1) {
        s  += __shfl_xor_sync(0xffffffffu, s, o);
        ss += __shfl_xor_sync(0xffffffffu, ss, o);
    }
    __shared__ float sm[16];
    if ((tid & 31) == 0) { sm[tid >> 5] = s; sm[8 + (tid >> 5)] = ss; }
    __syncthreads();
    float S = 0.f, SS = 0.f;
#pragma unroll
    for (int i = 0; i < 8; i++) { S += sm[i]; SS += sm[8 + i]; }
    const float mu  = S * (1.f / 1024.f);
    const float var = SS * (1.f / 1024.f) - mu * mu;
    const float rs  = rsqrtf(var + 1e-5f);

    const float4 gv = ((const float4*)g)[tid];
    const float4 bv = ((const float4*)b)[tid];
    float4 o;
    o.x = (xv.x - mu) * rs * gv.x + bv.x;
    o.y = (xv.y - mu) * rs * gv.y + bv.y;
    o.z = (xv.z - mu) * rs * gv.z + bv.z;
    o.w = (xv.w - mu) * rs * gv.w + bv.w;
    ((float4*)(out + (size_t)row * 1024))[tid] = o;
}

// ---------------------------------------------------------------------------
// Causal softmax with skewed relative bias:
//   P[q][k] = softmax_k<=q( (S[q][k] + QEr[q][k-q+1023]) / sqrt(128) ), 0 for k>q
// One block per (q, bh). In-place on S.
// ---------------------------------------------------------------------------
__global__ void __launch_bounds__(256)
softmax_kernel(const float* __restrict__ S, const float* __restrict__ E,
               float* __restrict__ P)
{
    const int q  = blockIdx.x;
    const int bh = blockIdx.y;
    const size_t base = ((size_t)bh * 1024 + q) * 1024;
    const int tid = threadIdx.x;
    const float scale = 0.08838834764831845f;  // 1/sqrt(128)

    float v[4];
    float mx = -3.4e38f;
#pragma unroll
    for (int i = 0; i < 4; i++) {
        const int k = tid + i * 256;
        float val = -3.4e38f;
        if (k <= q) val = (S[base + k] + E[base + k - q + 1023]) * scale;
        v[i] = val;
        mx = fmaxf(mx, val);
    }
#pragma unroll
    for (int o = 16; o; o >>= 1) mx = fmaxf(mx, __shfl_xor_sync(0xffffffffu, mx, o));
    __shared__ float red[8];
    if ((tid & 31) == 0) red[tid >> 5] = mx;
    __syncthreads();
    float m2 = red[0];
#pragma unroll
    for (int i = 1; i < 8; i++) m2 = fmaxf(m2, red[i]);
    __syncthreads();

    float sum = 0.f;
#pragma unroll
    for (int i = 0; i < 4; i++) {
        const float e = (v[i] > -1e37f) ? expf(v[i] - m2) : 0.f;
        v[i] = e;
        sum += e;
    }
#pragma unroll
    for (int o = 16; o; o >>= 1) sum += __shfl_xor_sync(0xffffffffu, sum, o);
    if ((tid & 31) == 0) red[tid >> 5] = sum;
    __syncthreads();
    float tot = 0.f;
#pragma unroll
    for (int i = 0; i < 8; i++) tot += red[i];
    const float inv = 1.f / tot;
#pragma unroll
    for (int i = 0; i < 4; i++) {
        const int k = tid + i * 256;
        P[base + k] = v[i] * inv;
    }
}

// ---------------------------------------------------------------------------
extern "C" void kernel_launch(void* const* d_in, const int* in_sizes, int n_in,
                              void* d_out, int out_size)
{
    (void)in_sizes; (void)n_in; (void)out_size;
    const float* x      = (const float*)d_in[0];
    const float* W_qkv  = (const float*)d_in[1];
    const float* b_qkv  = (const float*)d_in[2];
    const float* W_o    = (const float*)d_in[3];
    const float* b_o    = (const float*)d_in[4];
    const float* Er     = (const float*)d_in[5];
    const float* ln1_g  = (const float*)d_in[6];
    const float* ln1_b  = (const float*)d_in[7];
    const float* ln2_g  = (const float*)d_in[8];
    const float* ln2_b  = (const float*)d_in[9];
    const float* W_fc   = (const float*)d_in[10];
    const float* b_fc   = (const float*)d_in[11];
    const float* W_proj = (const float*)d_in[12];
    const float* b_proj = (const float*)d_in[13];
    float* out = (float*)d_out;

    float *ln, *qkv, *sc, *qer, *yb, *hb;
    cudaGetSymbolAddress((void**)&ln,  g_ln);
    cudaGetSymbolAddress((void**)&qkv, g_qkv);
    cudaGetSymbolAddress((void**)&sc,  g_scores);
    cudaGetSymbolAddress((void**)&qer, g_qer);
    cudaGetSymbolAddress((void**)&yb,  g_y);
    cudaGetSymbolAddress((void**)&hb,  g_h);

    const long long sq_hi = 1024LL * 3072;   // per-b stride inside qkv
    const long long sq_lo = 128LL;           // per-head stride inside qkv
    const long long ss_hi = 8LL * 1024 * 1024;  // per-b stride in scores/qer
    const long long ss_lo = 1024LL * 1024;      // per-head stride

    // 1) LN1
    ln_kernel<<<8192, 256>>>(x, ln1_g, ln1_b, ln);

    // 2) QKV = ln @ W_qkv + b_qkv          (8192 x 3072 x 1024)
    gemm_kernel<false><<<dim3(48, 128, 1), 256>>>(
        ln, 1024, 0, 0, W_qkv, 3072, 0, 0, qkv, 3072, 0, 0,
        8192, 3072, 1024, b_qkv, nullptr, 1, 0);

    // 3) QEr[bh] = q @ Er^T                (batched 64, 1024x1024x128, anti-tri skip)
    gemm_kernel<true><<<dim3(16, 16, 64), 256>>>(
        qkv, 3072, sq_hi, sq_lo, Er, 128, 0, 0, qer, 1024, ss_hi, ss_lo,
        1024, 1024, 128, nullptr, nullptr, 0, 2);

    // 4) S[bh] = q @ k^T                   (batched 64, lower-tri only)
    gemm_kernel<true><<<dim3(16, 16, 64), 256>>>(
        qkv, 3072, sq_hi, sq_lo, qkv + 1024, 3072, sq_hi, sq_lo, sc, 1024, ss_hi, ss_lo,
        1024, 1024, 128, nullptr, nullptr, 0, 1);

    // 5) P = causal softmax((S + skew(QEr)) / sqrt(hs))   (in-place)
    softmax_kernel<<<dim3(1024, 64), 256>>>(sc, qer, sc);

    // 6) y[bh] = P @ v                     (batched 64, 1024x128x1024, causal K)
    gemm_kernel<false><<<dim3(2, 16, 64), 256>>>(
        sc, 1024, ss_hi, ss_lo, qkv + 2048, 3072, sq_hi, sq_lo,
        yb, 1024, 1024LL * 1024, 128,
        1024, 128, 1024, nullptr, nullptr, 0, 3);

    // 7) x1 = x + y @ W_o + b_o            (8192 x 1024 x 1024) -> d_out
    gemm_kernel<false><<<dim3(16, 128, 1), 256>>>(
        yb, 1024, 0, 0, W_o, 1024, 0, 0, out, 1024, 0, 0,
        8192, 1024, 1024, b_o, x, 3, 0);

    // 8) LN2
    ln_kernel<<<8192, 256>>>(out, ln2_g, ln2_b, ln);

    // 9) h = gelu(ln @ W_fc + b_fc)        (8192 x 4096 x 1024)
    gemm_kernel<false><<<dim3(64, 128, 1), 256>>>(
        ln, 1024, 0, 0, W_fc, 4096, 0, 0, hb, 4096, 0, 0,
        8192, 4096, 1024, b_fc, nullptr, 2, 0);

    // 10) out = x1 + h @ W_proj + b_proj   (8192 x 1024 x 4096)
    gemm_kernel<false><<<dim3(16, 128, 1), 256>>>(
        hb, 4096, 0, 0, W_proj, 1024, 0, 0, out, 1024, 0, 0,
        8192, 1024, 4096, b_proj, out, 3, 0);
}

// round 2
// speedup vs baseline: 2.4564x; 2.4564x over previous
#include <cuda_runtime.h>
#include <math.h>
#include <stdint.h>

// Problem constants: B=8, L=1024, D=1024, F=4096, nh=8, hs=128, M=B*L=8192
#define BM 128
#define BN 128
#define BKt 16

// Scratch (static device globals; no runtime allocation)
__device__ float g_ln[8388608];        // 8192*1024   LN output
__device__ float g_qkv[25165824];      // 8192*3072   QKV
__device__ float g_scores[67108864];   // 64*1024*1024  S then P
__device__ float g_qer[67108864];      // 64*1024*1024  QEr
__device__ float g_y[8388608];         // 8192*1024   attention output
__device__ float g_h[33554432];        // 8192*4096   MLP hidden

__device__ __forceinline__ uint32_t f2tf(float x) {
    uint32_t u;
    asm("cvt.rna.tf32.f32 %0, %1;" : "=r"(u) : "f"(x));
    return u;
}

__device__ __forceinline__ void mma_tf32(float c[4],
    uint32_t a0, uint32_t a1, uint32_t a2, uint32_t a3,
    uint32_t b0, uint32_t b1)
{
    asm volatile(
        "mma.sync.aligned.m16n8k8.row.col.f32.tf32.tf32.f32 "
        "{%0,%1,%2,%3}, {%4,%5,%6,%7}, {%8,%9}, {%0,%1,%2,%3};"
        : "+f"(c[0]), "+f"(c[1]), "+f"(c[2]), "+f"(c[3])
        : "r"(a0), "r"(a1), "r"(a2), "r"(a3), "r"(b0), "r"(b1));
}

// ---------------------------------------------------------------------------
// tf32 tensor-core GEMM: C = A(MxK) * op(B) (+bias)(+gelu/+residual)
//   TRANSB=false: B is KxN row-major.  TRANSB=true: B is NxK row-major.
// Batched via blockIdx.z: z -> hi=z/8, lo=z%8.
// epilogue: 0=none, 1=+bias, 2=+bias+GELU, 3=+bias+residual
// tri: 0=full, 1=lower-tri tile skip, 2=anti-tri tile skip, 3=causal K bound
// Block tile 128x128, k-step 16; 8 warps as 2(m) x 4(n), warp tile 64x32.
// ---------------------------------------------------------------------------
template <bool TRANSB>
__global__ void __launch_bounds__(256, 2)
gemm_tf32(const float* __restrict__ A, int lda, long long sAhi, long long sAlo,
          const float* __restrict__ Bm, int ldb, long long sBhi, long long sBlo,
          float* __restrict__ C, int ldc, long long sChi, long long sClo,
          int N, int K,
          const float* __restrict__ bias, const float* __restrict__ resid,
          int epilogue, int tri)
{
    const int n0 = blockIdx.x * BN;
    const int m0 = blockIdx.y * BM;
    if (tri == 1 && n0 > m0) return;
    if (tri == 2 && (m0 + n0) < (N - BM - BN + 1)) return;
    const int kmax = (tri == 3) ? min(K, m0 + BM) : K;

    const int z = blockIdx.z, hi = z >> 3, lo = z & 7;
    A  += hi * sAhi + lo * sAlo;
    Bm += hi * sBhi + lo * sBlo;
    const long long coff = hi * sChi + lo * sClo;

    // Swizzled smem (tf32 bit patterns):
    //   As[r][k ^ (((r>>1)&3)<<2)]   (A as [m][k], 16 k per row)
    //   Bs[k][n ^ ((k&3)<<3)]        (B as [k][n], 128 n per row)
    __shared__ uint32_t As[128][16];
    __shared__ uint32_t Bs[16][128];

    const int tid  = threadIdx.x;
    const int lane = tid & 31;
    const int warp = tid >> 5;
    const int g  = lane >> 2;   // 0..7
    const int tg = lane & 3;    // 0..3
    const int wm = (warp >> 2) * 64;
    const int wn = (warp & 3) * 32;

    // A staging: row ra, k-half ka
    const int ra = tid >> 1;
    const int ka = (tid & 1) * 8;
    const float* Ap = A + (size_t)(m0 + ra) * lda + ka;

    // B staging
    int rb, kb;
    const float* Bp;
    if (TRANSB) {               // B row-major NxK: load along k
        rb = tid >> 1;          // n index 0..127
        kb = (tid & 1) * 8;     // k-half
        Bp = Bm + (size_t)(n0 + rb) * ldb + kb;
    } else {                    // B row-major KxN: load along n
        rb = tid >> 4;          // k row 0..15
        kb = (tid & 15) * 8;    // n offset
        Bp = Bm + (size_t)rb * ldb + n0 + kb;
    }

    float4 aR0, aR1, bR0, bR1;

    float acc[4][4][4] = {};

    // prologue: tile 0
    aR0 = *(const float4*)(Ap);
    aR1 = *(const float4*)(Ap + 4);
    if (TRANSB) {
        bR0 = *(const float4*)(Bp);
        bR1 = *(const float4*)(Bp + 4);
    } else {
        bR0 = *(const float4*)(Bp);
        bR1 = *(const float4*)(Bp + 4);
    }
    {
        const int msk = ((ra >> 1) & 3) << 2;
        uint32_t* d0 = &As[ra][ka ^ msk];
        d0[0] = f2tf(aR0.x); d0[1] = f2tf(aR0.y); d0[2] = f2tf(aR0.z); d0[3] = f2tf(aR0.w);
        uint32_t* d1 = &As[ra][(ka + 4) ^ msk];
        d1[0] = f2tf(aR1.x); d1[1] = f2tf(aR1.y); d1[2] = f2tf(aR1.z); d1[3] = f2tf(aR1.w);
    }
    if (TRANSB) {
        float v[8] = {bR0.x, bR0.y, bR0.z, bR0.w, bR1.x, bR1.y, bR1.z, bR1.w};
#pragma unroll
        for (int e = 0; e < 8; e++) {
            const int k = kb + e;
            Bs[k][rb ^ ((k & 3) << 3)] = f2tf(v[e]);
        }
    } else {
        const int msk = (rb & 3) << 3;
        uint32_t* d0 = &Bs[rb][kb ^ msk];
        d0[0] = f2tf(bR0.x); d0[1] = f2tf(bR0.y); d0[2] = f2tf(bR0.z); d0[3] = f2tf(bR0.w);
        uint32_t* d1 = &Bs[rb][(kb + 4) ^ msk];
        d1[0] = f2tf(bR1.x); d1[1] = f2tf(bR1.y); d1[2] = f2tf(bR1.z); d1[3] = f2tf(bR1.w);
    }
    __syncthreads();

    for (int k0 = 0; k0 < kmax; k0 += BKt) {
        const bool nxt = (k0 + BKt) < kmax;
        if (nxt) {
            aR0 = *(const float4*)(Ap + k0 + BKt);
            aR1 = *(const float4*)(Ap + k0 + BKt + 4);
            if (TRANSB) {
                bR0 = *(const float4*)(Bp + k0 + BKt);
                bR1 = *(const float4*)(Bp + k0 + BKt + 4);
            } else {
                bR0 = *(const float4*)(Bp + (size_t)(k0 + BKt) * ldb);
                bR1 = *(const float4*)(Bp + (size_t)(k0 + BKt) * ldb + 4);
            }
        }
#pragma unroll
        for (int k8 = 0; k8 < 16; k8 += 8) {
            uint32_t af[4][4], bf[4][2];
#pragma unroll
            for (int mt = 0; mt < 4; mt++) {
                const int r0 = wm + mt * 16 + g;
                const int r1 = r0 + 8;
                const int kk = k8 + tg;
                const int m0k = ((r0 >> 1) & 3) << 2;   // same for r1 (r1=r0+8)
                af[mt][0] = As[r0][kk ^ m0k];
                af[mt][1] = As[r1][kk ^ m0k];
                af[mt][2] = As[r0][(kk + 4) ^ m0k];
                af[mt][3] = As[r1][(kk + 4) ^ m0k];
            }
#pragma unroll
            for (int nt = 0; nt < 4; nt++) {
                const int n = wn + nt * 8 + g;
                bf[nt][0] = Bs[k8 + tg][n ^ (tg << 3)];
                bf[nt][1] = Bs[k8 + tg + 4][n ^ (tg << 3)];
            }
#pragma unroll
            for (int mt = 0; mt < 4; mt++)
#pragma unroll
                for (int nt = 0; nt < 4; nt++)
                    mma_tf32(acc[mt][nt],
                             af[mt][0], af[mt][1], af[mt][2], af[mt][3],
                             bf[nt][0], bf[nt][1]);
        }
        __syncthreads();
        if (nxt) {
            {
                const int msk = ((ra >> 1) & 3) << 2;
                uint32_t* d0 = &As[ra][ka ^ msk];
                d0[0] = f2tf(aR0.x); d0[1] = f2tf(aR0.y); d0[2] = f2tf(aR0.z); d0[3] = f2tf(aR0.w);
                uint32_t* d1 = &As[ra][(ka + 4) ^ msk];
                d1[0] = f2tf(aR1.x); d1[1] = f2tf(aR1.y); d1[2] = f2tf(aR1.z); d1[3] = f2tf(aR1.w);
            }
            if (TRANSB) {
                float v[8] = {bR0.x, bR0.y, bR0.z, bR0.w, bR1.x, bR1.y, bR1.z, bR1.w};
#pragma unroll
                for (int e = 0; e < 8; e++) {
                    const int k = kb + e;
                    Bs[k][rb ^ ((k & 3) << 3)] = f2tf(v[e]);
                }
            } else {
                const int msk = (rb & 3) << 3;
                uint32_t* d0 = &Bs[rb][kb ^ msk];
                d0[0] = f2tf(bR0.x); d0[1] = f2tf(bR0.y); d0[2] = f2tf(bR0.z); d0[3] = f2tf(bR0.w);
                uint32_t* d1 = &Bs[rb][(kb + 4) ^ msk];
                d1[0] = f2tf(bR1.x); d1[1] = f2tf(bR1.y); d1[2] = f2tf(bR1.z); d1[3] = f2tf(bR1.w);
            }
            __syncthreads();
        }
    }

    // Epilogue
#pragma unroll
    for (int mt = 0; mt < 4; mt++) {
#pragma unroll
        for (int nt = 0; nt < 4; nt++) {
            const int r  = m0 + wm + mt * 16 + g;
            const int cb = n0 + wn + nt * 8 + tg * 2;
            float b0 = 0.f, b1 = 0.f;
            if (epilogue) { b0 = bias[cb]; b1 = bias[cb + 1]; }
            float o00 = acc[mt][nt][0] + b0, o01 = acc[mt][nt][1] + b1;
            float o10 = acc[mt][nt][2] + b0, o11 = acc[mt][nt][3] + b1;
            const size_t i0 = (size_t)coff + (size_t)r * ldc + cb;
            const size_t i1 = (size_t)coff + (size_t)(r + 8) * ldc + cb;
            if (epilogue == 2) {
                o00 *= normcdff(o00); o01 *= normcdff(o01);
                o10 *= normcdff(o10); o11 *= normcdff(o11);
            } else if (epilogue == 3) {
                const float2 r0 = *(const float2*)(resid + i0);
                const float2 r1 = *(const float2*)(resid + i1);
                o00 += r0.x; o01 += r0.y; o10 += r1.x; o11 += r1.y;
            }
            float2 s0 = make_float2(o00, o01);
            float2 s1 = make_float2(o10, o11);
            *(float2*)(C + i0) = s0;
            *(float2*)(C + i1) = s1;
        }
    }
}

// ---------------------------------------------------------------------------
// LayerNorm over rows of length 1024. One block (256 threads) per row.
// ---------------------------------------------------------------------------
__global__ void __launch_bounds__(256)
ln_kernel(const float* __restrict__ x, const float* __restrict__ g,
          const float* __restrict__ b, float* __restrict__ out)
{
    const int row = blockIdx.x;
    const int tid = threadIdx.x;
    const float4 xv = ((const float4*)(x + (size_t)row * 1024))[tid];

    float s  = xv.x + xv.y + xv.z + xv.w;
    float ss = xv.x * xv.x + xv.y * xv.y + xv.z * xv.z + xv.w * xv.w;
#pragma unroll
    for (int o = 16; o; o >>= 1) {
        s  += __shfl_xor_sync(0xffffffffu, s, o);
        ss += __shfl_xor_sync(0xffffffffu, ss, o);
    }
    __shared__ float sm[16];
    if ((tid & 31) == 0) { sm[tid >> 5] = s; sm[8 + (tid >> 5)] = ss; }
    __syncthreads();
    float S = 0.f, SS = 0.f;
#pragma unroll
    for (int i = 0; i < 8; i++) { S += sm[i]; SS += sm[8 + i]; }
    const float mu  = S * (1.f / 1024.f);
    const float var = SS * (1.f / 1024.f) - mu * mu;
    const float rs  = rsqrtf(var + 1e-5f);

    const float4 gv = ((const float4*)g)[tid];
    const float4 bv = ((const float4*)b)[tid];
    float4 o;
    o.x = (xv.x - mu) * rs * gv.x + bv.x;
    o.y = (xv.y - mu) * rs * gv.y + bv.y;
    o.z = (xv.z - mu) * rs * gv.z + bv.z;
    o.w = (xv.w - mu) * rs * gv.w + bv.w;
    ((float4*)(out + (size_t)row * 1024))[tid] = o;
}

// ---------------------------------------------------------------------------
// Causal softmax with skewed relative bias (in-place on S).
// ---------------------------------------------------------------------------
__global__ void __launch_bounds__(256)
softmax_kernel(const float* __restrict__ S, const float* __restrict__ E,
               float* __restrict__ P)
{
    const int q  = blockIdx.x;
    const int bh = blockIdx.y;
    const size_t base = ((size_t)bh * 1024 + q) * 1024;
    const int tid = threadIdx.x;
    const float scale = 0.08838834764831845f;  // 1/sqrt(128)

    float v[4];
    float mx = -3.4e38f;
#pragma unroll
    for (int i = 0; i < 4; i++) {
        const int k = tid + i * 256;
        float val = -3.4e38f;
        if (k <= q) val = (S[base + k] + E[base + k - q + 1023]) * scale;
        v[i] = val;
        mx = fmaxf(mx, val);
    }
#pragma unroll
    for (int o = 16; o; o >>= 1) mx = fmaxf(mx, __shfl_xor_sync(0xffffffffu, mx, o));
    __shared__ float red[8];
    if ((tid & 31) == 0) red[tid >> 5] = mx;
    __syncthreads();
    float m2 = red[0];
#pragma unroll
    for (int i = 1; i < 8; i++) m2 = fmaxf(m2, red[i]);
    __syncthreads();

    float sum = 0.f;
#pragma unroll
    for (int i = 0; i < 4; i++) {
        const float e = (v[i] > -1e37f) ? expf(v[i] - m2) : 0.f;
        v[i] = e;
        sum += e;
    }
#pragma unroll
    for (int o = 16; o; o >>= 1) sum += __shfl_xor_sync(0xffffffffu, sum, o);
    if ((tid & 31) == 0) red[tid >> 5] = sum;
    __syncthreads();
    float tot = 0.f;
#pragma unroll
    for (int i = 0; i < 8; i++) tot += red[i];
    const float inv = 1.f / tot;
#pragma unroll
    for (int i = 0; i < 4; i++) {
        const int k = tid + i * 256;
        P[base + k] = v[i] * inv;
    }
}

// ---------------------------------------------------------------------------
extern "C" void kernel_launch(void* const* d_in, const int* in_sizes, int n_in,
                              void* d_out, int out_size)
{
    (void)in_sizes; (void)n_in; (void)out_size;
    const float* x      = (const float*)d_in[0];
    const float* W_qkv  = (const float*)d_in[1];
    const float* b_qkv  = (const float*)d_in[2];
    const float* W_o    = (const float*)d_in[3];
    const float* b_o    = (const float*)d_in[4];
    const float* Er     = (const float*)d_in[5];
    const float* ln1_g  = (const float*)d_in[6];
    const float* ln1_b  = (const float*)d_in[7];
    const float* ln2_g  = (const float*)d_in[8];
    const float* ln2_b  = (const float*)d_in[9];
    const float* W_fc   = (const float*)d_in[10];
    const float* b_fc   = (const float*)d_in[11];
    const float* W_proj = (const float*)d_in[12];
    const float* b_proj = (const float*)d_in[13];
    float* out = (float*)d_out;

    float *ln, *qkv, *sc, *qer, *yb, *hb;
    cudaGetSymbolAddress((void**)&ln,  g_ln);
    cudaGetSymbolAddress((void**)&qkv, g_qkv);
    cudaGetSymbolAddress((void**)&sc,  g_scores);
    cudaGetSymbolAddress((void**)&qer, g_qer);
    cudaGetSymbolAddress((void**)&yb,  g_y);
    cudaGetSymbolAddress((void**)&hb,  g_h);

    const long long sq_hi = 1024LL * 3072;      // per-b stride inside qkv
    const long long sq_lo = 128LL;               // per-head stride inside qkv
    const long long ss_hi = 8LL * 1024 * 1024;   // per-b stride in scores/qer
    const long long ss_lo = 1024LL * 1024;       // per-head stride

    // 1) LN1
    ln_kernel<<<8192, 256>>>(x, ln1_g, ln1_b, ln);

    // 2) QKV = ln @ W_qkv + b_qkv          (8192 x 3072 x 1024)
    gemm_tf32<false><<<dim3(24, 64, 1), 256>>>(
        ln, 1024, 0, 0, W_qkv, 3072, 0, 0, qkv, 3072, 0, 0,
        3072, 1024, b_qkv, nullptr, 1, 0);

    // 3) QEr[bh] = q @ Er^T                (batched 64, anti-tri skip)
    gemm_tf32<true><<<dim3(8, 8, 64), 256>>>(
        qkv, 3072, sq_hi, sq_lo, Er, 128, 0, 0, qer, 1024, ss_hi, ss_lo,
        1024, 128, nullptr, nullptr, 0, 2);

    // 4) S[bh] = q @ k^T                   (batched 64, lower-tri only)
    gemm_tf32<true><<<dim3(8, 8, 64), 256>>>(
        qkv, 3072, sq_hi, sq_lo, qkv + 1024, 3072, sq_hi, sq_lo, sc, 1024, ss_hi, ss_lo,
        1024, 128, nullptr, nullptr, 0, 1);

    // 5) P = causal softmax((S + skew(QEr)) / sqrt(hs))   (in-place)
    softmax_kernel<<<dim3(1024, 64), 256>>>(sc, qer, sc);

    // 6) y[bh] = P @ v                     (batched 64, causal K bound)
    gemm_tf32<false><<<dim3(1, 8, 64), 256>>>(
        sc, 1024, ss_hi, ss_lo, qkv + 2048, 3072, sq_hi, sq_lo,
        yb, 1024, 1024LL * 1024, 128,
        128, 1024, nullptr, nullptr, 0, 3);

    // 7) x1 = x + y @ W_o + b_o            (8192 x 1024 x 1024) -> d_out
    gemm_tf32<false><<<dim3(8, 64, 1), 256>>>(
        yb, 1024, 0, 0, W_o, 1024, 0, 0, out, 1024, 0, 0,
        1024, 1024, b_o, x, 3, 0);

    // 8) LN2
    ln_kernel<<<8192, 256>>>(out, ln2_g, ln2_b, ln);

    // 9) h = gelu(ln @ W_fc + b_fc)        (8192 x 4096 x 1024)
    gemm_tf32<false><<<dim3(32, 64, 1), 256>>>(
        ln, 1024, 0, 0, W_fc, 4096, 0, 0, hb, 4096, 0, 0,
        4096, 1024, b_fc, nullptr, 2, 0);

    // 10) out = x1 + h @ W_proj + b_proj   (8192 x 1024 x 4096)
    gemm_tf32<false><<<dim3(8, 64, 1), 256>>>(
        hb, 4096, 0, 0, W_proj, 1024, 0, 0, out, 1024, 0, 0,
        1024, 4096, b_proj, out, 3, 0);
}